// round 4
// baseline (speedup 1.0000x reference)
#include <cuda_runtime.h>
#include <math.h>

#define S_FR   16
#define P_TOK  512
#define C_DIM  768
#define H_HEADS 12
#define K_COV  6
#define D_DIM  64
#define N_TOK  8192
#define QKV_N  2304

// Scratch (allocation-free: __device__ globals)
__device__ float g_q[H_HEADS * N_TOK * D_DIM];
__device__ float g_k[H_HEADS * N_TOK * D_DIM];
__device__ float g_v[H_HEADS * N_TOK * D_DIM];
__device__ float g_attn[N_TOK * C_DIM];

__device__ __forceinline__ unsigned f2tf(float f) {
  unsigned u;
  asm("cvt.rna.tf32.f32 %0, %1;" : "=r"(u) : "f"(f));
  return u;
}
__device__ __forceinline__ float ex2(float x) {
  float y;
  asm("ex2.approx.ftz.f32 %0, %1;" : "=f"(y) : "f"(x));
  return y;
}
__device__ __forceinline__ void mma8(float c[4], const unsigned a[4],
                                     const unsigned b[2]) {
  asm volatile(
      "mma.sync.aligned.m16n8k8.row.col.f32.tf32.tf32.f32 "
      "{%0,%1,%2,%3},{%4,%5,%6,%7},{%8,%9},{%0,%1,%2,%3};\n"
      : "+f"(c[0]), "+f"(c[1]), "+f"(c[2]), "+f"(c[3])
      : "r"(a[0]), "r"(a[1]), "r"(a[2]), "r"(a[3]), "r"(b[0]), "r"(b[1]));
}
__device__ __forceinline__ uint4 tf4(float4 v) {
  uint4 t;
  t.x = f2tf(v.x); t.y = f2tf(v.y); t.z = f2tf(v.z); t.w = f2tf(v.w);
  return t;
}

// ---------------------------------------------------------------------------
// TF32 mma GEMM (unchanged from round 3): C = A[M,768]*B[768,N] + bias
// ---------------------------------------------------------------------------
#define AST 20
#define BST 136

template <int MODE>
__global__ __launch_bounds__(256) void gemm_mma(
    const float* __restrict__ A, const float* __restrict__ B,
    const float* __restrict__ bias, float* __restrict__ Cout, int Ncols) {
  __shared__ unsigned As[128 * AST];
  __shared__ unsigned Bs[16 * BST];
  const int tid = threadIdx.x;
  const int warp = tid >> 5, lane = tid & 31;
  const int gid = lane >> 2, tig = lane & 3;
  const int wm = warp >> 2, wn = warp & 3;
  const int bn = blockIdx.x, bm = blockIdx.y;

  const float* Ap = (MODE == 1) ? (const float*)g_attn : A;
  const float* Ab = Ap + (size_t)(bm * 128) * C_DIM;
  const float* Bb = B + bn * 128;

  const int arow = tid >> 2, acol = (tid & 3) << 2;
  const int brow = tid >> 5, bcol = (tid & 31) << 2;

  float acc[16][4];
#pragma unroll
  for (int i = 0; i < 16; i++)
#pragma unroll
    for (int j = 0; j < 4; j++) acc[i][j] = 0.f;

  float4 pa0, pa1, pb0, pb1;
  pa0 = *(const float4*)&Ab[(size_t)arow * C_DIM + acol];
  pa1 = *(const float4*)&Ab[(size_t)(arow + 64) * C_DIM + acol];
  pb0 = *(const float4*)&Bb[(size_t)brow * Ncols + bcol];
  pb1 = *(const float4*)&Bb[(size_t)(brow + 8) * Ncols + bcol];

  const int NT = C_DIM / 16;
  for (int t = 0; t < NT; t++) {
    __syncthreads();
    *(uint4*)&As[arow * AST + acol] = tf4(pa0);
    *(uint4*)&As[(arow + 64) * AST + acol] = tf4(pa1);
    *(uint4*)&Bs[brow * BST + bcol] = tf4(pb0);
    *(uint4*)&Bs[(brow + 8) * BST + bcol] = tf4(pb1);
    __syncthreads();

    if (t + 1 < NT) {
      const int k0 = (t + 1) * 16;
      pa0 = *(const float4*)&Ab[(size_t)arow * C_DIM + k0 + acol];
      pa1 = *(const float4*)&Ab[(size_t)(arow + 64) * C_DIM + k0 + acol];
      pb0 = *(const float4*)&Bb[(size_t)(k0 + brow) * Ncols + bcol];
      pb1 = *(const float4*)&Bb[(size_t)(k0 + brow + 8) * Ncols + bcol];
    }

#pragma unroll
    for (int ks = 0; ks < 2; ks++) {
      const int k = ks * 8;
      unsigned af[4][4], bf[4][2];
#pragma unroll
      for (int mt = 0; mt < 4; mt++) {
        const int m = wm * 64 + mt * 16 + gid;
        af[mt][0] = As[m * AST + k + tig];
        af[mt][1] = As[(m + 8) * AST + k + tig];
        af[mt][2] = As[m * AST + k + tig + 4];
        af[mt][3] = As[(m + 8) * AST + k + tig + 4];
      }
#pragma unroll
      for (int nt = 0; nt < 4; nt++) {
        const int n = wn * 32 + nt * 8 + gid;
        bf[nt][0] = Bs[(k + tig) * BST + n];
        bf[nt][1] = Bs[(k + tig + 4) * BST + n];
      }
#pragma unroll
      for (int mt = 0; mt < 4; mt++)
#pragma unroll
        for (int nt = 0; nt < 4; nt++) mma8(acc[mt * 4 + nt], af[mt], bf[nt]);
    }
  }

#pragma unroll
  for (int mt = 0; mt < 4; mt++) {
#pragma unroll
    for (int nt = 0; nt < 4; nt++) {
      const int row = bm * 128 + wm * 64 + mt * 16 + gid;
      const int col = bn * 128 + wn * 32 + nt * 8 + 2 * tig;
      const float b0 = bias[col], b1 = bias[col + 1];
      float2 lo, hi;
      lo.x = acc[mt * 4 + nt][0] + b0;
      lo.y = acc[mt * 4 + nt][1] + b1;
      hi.x = acc[mt * 4 + nt][2] + b0;
      hi.y = acc[mt * 4 + nt][3] + b1;
      if (MODE == 0) {
        const int which = col / C_DIM;
        const int rem = col - which * C_DIM;
        const int h = rem >> 6, d = rem & 63;
        float* dst = (which == 0) ? g_q : (which == 1 ? g_k : g_v);
        *(float2*)&dst[((size_t)h * N_TOK + row) * D_DIM + d] = lo;
        *(float2*)&dst[((size_t)h * N_TOK + row + 8) * D_DIM + d] = hi;
      } else {
        *(float2*)&Cout[(size_t)row * C_DIM + col] = lo;
        *(float2*)&Cout[(size_t)(row + 8) * C_DIM + col] = hi;
      }
    }
  }
}

// ---------------------------------------------------------------------------
// TF32 mma flash attention, 32 q-rows per warp (2 m-tiles share b-frags).
// Block = (256-query tile, head, frame), 8 warps. Key tiles of 64, 48 tiles.
// ---------------------------------------------------------------------------
#define QST 68   // Qs/Ps stride: bank = row*4+tig, conflict-free
#define KST 68   // Ks stride: k b-frag bank = gid*4+tig, conflict-free
#define VST 72   // Vs stride: v b-frag bank = tig*8+gid, conflict-free
#define QROWS 256
#define ATTN_SMEM ((QROWS * QST + 64 * KST + 64 * VST + QROWS * QST) * 4)

__global__ __launch_bounds__(256, 1) void attn_kernel(
    const int* __restrict__ covis) {
  extern __shared__ unsigned sm[];
  unsigned* Qs = sm;                     // [256][QST]
  unsigned* Ks = Qs + QROWS * QST;       // [64][KST] key-major
  unsigned* Vs = Ks + 64 * KST;          // [64][VST] key-major
  unsigned* Ps = Vs + 64 * VST;          // [256][QST]

  const int tid = threadIdx.x;
  const int warp = tid >> 5, lane = tid & 31;
  const int gid = lane >> 2, tig = lane & 3;
  const int qt = blockIdx.x, h = blockIdx.y, f = blockIdx.z;

  // Stage Q tile (fp32 -> tf32): 256 x 64
  const float* qptr =
      g_q + ((size_t)h * N_TOK + f * P_TOK + qt * QROWS) * D_DIM;
#pragma unroll
  for (int j = 0; j < 16; j++) {
    int i = j * 256 + tid;
    int row = i >> 4, c4 = (i & 15) << 2;
    *(uint4*)&Qs[row * QST + c4] = tf4(*(const float4*)&qptr[row * D_DIM + c4]);
  }

  float o[2][8][4];
#pragma unroll
  for (int mt = 0; mt < 2; mt++)
#pragma unroll
    for (int nb = 0; nb < 8; nb++)
#pragma unroll
      for (int j = 0; j < 4; j++) o[mt][nb][j] = 0.f;
  float mrow[2][2], lrow[2][2];
#pragma unroll
  for (int mt = 0; mt < 2; mt++) {
    mrow[mt][0] = -INFINITY; mrow[mt][1] = -INFINITY;
    lrow[mt][0] = 0.f; lrow[mt][1] = 0.f;
  }
  const float CS = 0.18033688011f;  // 0.125 * log2(e)

  const unsigned* Qw = Qs + warp * 32 * QST;
  unsigned* Pw = Ps + warp * 32 * QST;

  for (int t = 0; t < (K_COV * P_TOK) / 64; t++) {
    const int frame = covis[f * K_COV + (t >> 3)];
    const int off = (t & 7) << 6;
    const float* kp = g_k + ((size_t)h * N_TOK + frame * P_TOK + off) * D_DIM;
    const float* vp = g_v + ((size_t)h * N_TOK + frame * P_TOK + off) * D_DIM;

    __syncthreads();  // previous tile's Ks/Vs reads done
#pragma unroll
    for (int j = 0; j < 4; j++) {
      int i = j * 256 + tid;
      int key = i >> 4, c4 = (i & 15) << 2;
      *(uint4*)&Ks[key * KST + c4] = tf4(*(const float4*)&kp[key * D_DIM + c4]);
      *(uint4*)&Vs[key * VST + c4] = tf4(*(const float4*)&vp[key * D_DIM + c4]);
    }
    __syncthreads();

    // ---- S = Q K^T : warp computes 32x64 (2 m-tiles share b-frags) ----
    float s[2][8][4];
#pragma unroll
    for (int mt = 0; mt < 2; mt++)
#pragma unroll
      for (int nb = 0; nb < 8; nb++)
#pragma unroll
        for (int j = 0; j < 4; j++) s[mt][nb][j] = 0.f;
#pragma unroll
    for (int ks = 0; ks < 8; ks++) {
      unsigned a[2][4];
#pragma unroll
      for (int mt = 0; mt < 2; mt++) {
        const int r = mt * 16 + gid;
        a[mt][0] = Qw[r * QST + ks * 8 + tig];
        a[mt][1] = Qw[(r + 8) * QST + ks * 8 + tig];
        a[mt][2] = Qw[r * QST + ks * 8 + tig + 4];
        a[mt][3] = Qw[(r + 8) * QST + ks * 8 + tig + 4];
      }
#pragma unroll
      for (int nb = 0; nb < 8; nb++) {
        unsigned b[2];
        b[0] = Ks[(nb * 8 + gid) * KST + ks * 8 + tig];
        b[1] = Ks[(nb * 8 + gid) * KST + ks * 8 + tig + 4];
        mma8(s[0][nb], a[0], b);
        mma8(s[1][nb], a[1], b);
      }
    }

    // ---- online softmax (4 rows per thread) + P store ----
#pragma unroll
    for (int mt = 0; mt < 2; mt++) {
      float mx0 = -INFINITY, mx1 = -INFINITY;
#pragma unroll
      for (int nb = 0; nb < 8; nb++) {
        mx0 = fmaxf(mx0, fmaxf(s[mt][nb][0], s[mt][nb][1]));
        mx1 = fmaxf(mx1, fmaxf(s[mt][nb][2], s[mt][nb][3]));
      }
      mx0 = fmaxf(mx0, __shfl_xor_sync(0xffffffffu, mx0, 1));
      mx0 = fmaxf(mx0, __shfl_xor_sync(0xffffffffu, mx0, 2));
      mx1 = fmaxf(mx1, __shfl_xor_sync(0xffffffffu, mx1, 1));
      mx1 = fmaxf(mx1, __shfl_xor_sync(0xffffffffu, mx1, 2));
      const float nm0 = fmaxf(mrow[mt][0], mx0);
      const float nm1 = fmaxf(mrow[mt][1], mx1);
      const float rf0 = ex2((mrow[mt][0] - nm0) * CS);
      const float rf1 = ex2((mrow[mt][1] - nm1) * CS);
      mrow[mt][0] = nm0; mrow[mt][1] = nm1;

      float sum0 = 0.f, sum1 = 0.f;
      const int r = mt * 16 + gid;
#pragma unroll
      for (int nb = 0; nb < 8; nb++) {
        float p0 = ex2((s[mt][nb][0] - nm0) * CS);
        float p1 = ex2((s[mt][nb][1] - nm0) * CS);
        float p2 = ex2((s[mt][nb][2] - nm1) * CS);
        float p3 = ex2((s[mt][nb][3] - nm1) * CS);
        sum0 += p0 + p1;
        sum1 += p2 + p3;
        uint2 u01; u01.x = f2tf(p0); u01.y = f2tf(p1);
        uint2 u23; u23.x = f2tf(p2); u23.y = f2tf(p3);
        *(uint2*)&Pw[r * QST + nb * 8 + 2 * tig] = u01;
        *(uint2*)&Pw[(r + 8) * QST + nb * 8 + 2 * tig] = u23;
      }
      sum0 += __shfl_xor_sync(0xffffffffu, sum0, 1);
      sum0 += __shfl_xor_sync(0xffffffffu, sum0, 2);
      sum1 += __shfl_xor_sync(0xffffffffu, sum1, 1);
      sum1 += __shfl_xor_sync(0xffffffffu, sum1, 2);
      lrow[mt][0] = lrow[mt][0] * rf0 + sum0;
      lrow[mt][1] = lrow[mt][1] * rf1 + sum1;
#pragma unroll
      for (int nb = 0; nb < 8; nb++) {
        o[mt][nb][0] *= rf0; o[mt][nb][1] *= rf0;
        o[mt][nb][2] *= rf1; o[mt][nb][3] *= rf1;
      }
    }
    __syncwarp();  // P visible across the warp

    // ---- O += P V (2 m-tiles share V b-frags) ----
#pragma unroll
    for (int ks = 0; ks < 8; ks++) {
      unsigned a[2][4];
#pragma unroll
      for (int mt = 0; mt < 2; mt++) {
        const int r = mt * 16 + gid;
        a[mt][0] = Pw[r * QST + ks * 8 + tig];
        a[mt][1] = Pw[(r + 8) * QST + ks * 8 + tig];
        a[mt][2] = Pw[r * QST + ks * 8 + tig + 4];
        a[mt][3] = Pw[(r + 8) * QST + ks * 8 + tig + 4];
      }
#pragma unroll
      for (int nb = 0; nb < 8; nb++) {
        unsigned b[2];
        b[0] = Vs[(ks * 8 + tig) * VST + nb * 8 + gid];
        b[1] = Vs[(ks * 8 + tig + 4) * VST + nb * 8 + gid];
        mma8(o[0][nb], a[0], b);
        mma8(o[1][nb], a[1], b);
      }
    }
    __syncwarp();  // P reads done before next tile overwrites
  }

  // ---- finalize: O / l, write [N, H*D] ----
#pragma unroll
  for (int mt = 0; mt < 2; mt++) {
    const float inv0 = 1.f / lrow[mt][0], inv1 = 1.f / lrow[mt][1];
    const int tok0 = f * P_TOK + qt * QROWS + warp * 32 + mt * 16 + gid;
    float* op0 = g_attn + (size_t)tok0 * C_DIM + h * D_DIM;
    float* op1 = op0 + 8 * C_DIM;
#pragma unroll
    for (int nb = 0; nb < 8; nb++) {
      float2 w0, w1;
      w0.x = o[mt][nb][0] * inv0; w0.y = o[mt][nb][1] * inv0;
      w1.x = o[mt][nb][2] * inv1; w1.y = o[mt][nb][3] * inv1;
      *(float2*)&op0[nb * 8 + 2 * tig] = w0;
      *(float2*)&op1[nb * 8 + 2 * tig] = w1;
    }
  }
}

// ---------------------------------------------------------------------------
extern "C" void kernel_launch(void* const* d_in, const int* in_sizes, int n_in,
                              void* d_out, int out_size) {
  const float* x     = (const float*)d_in[0];
  const float* Wqkv  = (const float*)d_in[1];
  const float* bqkv  = (const float*)d_in[2];
  const float* Wproj = (const float*)d_in[3];
  const float* bproj = (const float*)d_in[4];
  const int*   covis = (const int*)d_in[5];
  float* out = (float*)d_out;
  (void)in_sizes; (void)n_in; (void)out_size;

  cudaFuncSetAttribute(attn_kernel, cudaFuncAttributeMaxDynamicSharedMemorySize,
                       ATTN_SMEM);

  gemm_mma<0><<<dim3(QKV_N / 128, N_TOK / 128), 256>>>(x, Wqkv, bqkv,
                                                       nullptr, QKV_N);
  attn_kernel<<<dim3(P_TOK / QROWS, H_HEADS, S_FR), 256, ATTN_SMEM>>>(covis);
  gemm_mma<1><<<dim3(C_DIM / 128, N_TOK / 128), 256>>>(nullptr, Wproj, bproj,
                                                       out, C_DIM);
}

// round 5
// speedup vs baseline: 1.4675x; 1.4675x over previous
#include <cuda_runtime.h>
#include <math.h>

#define S_FR   16
#define P_TOK  512
#define C_DIM  768
#define H_HEADS 12
#define K_COV  6
#define D_DIM  64
#define N_TOK  8192
#define QKV_N  2304

// Scratch (allocation-free: __device__ globals)
__device__ float g_q[H_HEADS * N_TOK * D_DIM];
__device__ float g_k[H_HEADS * N_TOK * D_DIM];
__device__ float g_v[H_HEADS * N_TOK * D_DIM];
__device__ float g_attn[N_TOK * C_DIM];

__device__ __forceinline__ unsigned f2tf(float f) {
  unsigned u;
  asm("cvt.rna.tf32.f32 %0, %1;" : "=r"(u) : "f"(f));
  return u;
}
__device__ __forceinline__ float ex2(float x) {
  float y;
  asm("ex2.approx.ftz.f32 %0, %1;" : "=f"(y) : "f"(x));
  return y;
}
__device__ __forceinline__ void mma8(float c[4], const unsigned a[4],
                                     const unsigned b[2]) {
  asm volatile(
      "mma.sync.aligned.m16n8k8.row.col.f32.tf32.tf32.f32 "
      "{%0,%1,%2,%3},{%4,%5,%6,%7},{%8,%9},{%0,%1,%2,%3};\n"
      : "+f"(c[0]), "+f"(c[1]), "+f"(c[2]), "+f"(c[3])
      : "r"(a[0]), "r"(a[1]), "r"(a[2]), "r"(a[3]), "r"(b[0]), "r"(b[1]));
}
__device__ __forceinline__ uint4 tf4(float4 v) {
  uint4 t;
  t.x = f2tf(v.x); t.y = f2tf(v.y); t.z = f2tf(v.z); t.w = f2tf(v.w);
  return t;
}

// ---------------------------------------------------------------------------
// TF32 mma GEMM (unchanged from round 3): C = A[M,768]*B[768,N] + bias
// ---------------------------------------------------------------------------
#define AST 20
#define BST 136

template <int MODE>
__global__ __launch_bounds__(256) void gemm_mma(
    const float* __restrict__ A, const float* __restrict__ B,
    const float* __restrict__ bias, float* __restrict__ Cout, int Ncols) {
  __shared__ unsigned As[128 * AST];
  __shared__ unsigned Bs[16 * BST];
  const int tid = threadIdx.x;
  const int warp = tid >> 5, lane = tid & 31;
  const int gid = lane >> 2, tig = lane & 3;
  const int wm = warp >> 2, wn = warp & 3;
  const int bn = blockIdx.x, bm = blockIdx.y;

  const float* Ap = (MODE == 1) ? (const float*)g_attn : A;
  const float* Ab = Ap + (size_t)(bm * 128) * C_DIM;
  const float* Bb = B + bn * 128;

  const int arow = tid >> 2, acol = (tid & 3) << 2;
  const int brow = tid >> 5, bcol = (tid & 31) << 2;

  float acc[16][4];
#pragma unroll
  for (int i = 0; i < 16; i++)
#pragma unroll
    for (int j = 0; j < 4; j++) acc[i][j] = 0.f;

  float4 pa0, pa1, pb0, pb1;
  pa0 = *(const float4*)&Ab[(size_t)arow * C_DIM + acol];
  pa1 = *(const float4*)&Ab[(size_t)(arow + 64) * C_DIM + acol];
  pb0 = *(const float4*)&Bb[(size_t)brow * Ncols + bcol];
  pb1 = *(const float4*)&Bb[(size_t)(brow + 8) * Ncols + bcol];

  const int NT = C_DIM / 16;
  for (int t = 0; t < NT; t++) {
    __syncthreads();
    *(uint4*)&As[arow * AST + acol] = tf4(pa0);
    *(uint4*)&As[(arow + 64) * AST + acol] = tf4(pa1);
    *(uint4*)&Bs[brow * BST + bcol] = tf4(pb0);
    *(uint4*)&Bs[(brow + 8) * BST + bcol] = tf4(pb1);
    __syncthreads();

    if (t + 1 < NT) {
      const int k0 = (t + 1) * 16;
      pa0 = *(const float4*)&Ab[(size_t)arow * C_DIM + k0 + acol];
      pa1 = *(const float4*)&Ab[(size_t)(arow + 64) * C_DIM + k0 + acol];
      pb0 = *(const float4*)&Bb[(size_t)(k0 + brow) * Ncols + bcol];
      pb1 = *(const float4*)&Bb[(size_t)(k0 + brow + 8) * Ncols + bcol];
    }

#pragma unroll
    for (int ks = 0; ks < 2; ks++) {
      const int k = ks * 8;
      unsigned af[4][4], bf[4][2];
#pragma unroll
      for (int mt = 0; mt < 4; mt++) {
        const int m = wm * 64 + mt * 16 + gid;
        af[mt][0] = As[m * AST + k + tig];
        af[mt][1] = As[(m + 8) * AST + k + tig];
        af[mt][2] = As[m * AST + k + tig + 4];
        af[mt][3] = As[(m + 8) * AST + k + tig + 4];
      }
#pragma unroll
      for (int nt = 0; nt < 4; nt++) {
        const int n = wn * 32 + nt * 8 + gid;
        bf[nt][0] = Bs[(k + tig) * BST + n];
        bf[nt][1] = Bs[(k + tig + 4) * BST + n];
      }
#pragma unroll
      for (int mt = 0; mt < 4; mt++)
#pragma unroll
        for (int nt = 0; nt < 4; nt++) mma8(acc[mt * 4 + nt], af[mt], bf[nt]);
    }
  }

#pragma unroll
  for (int mt = 0; mt < 4; mt++) {
#pragma unroll
    for (int nt = 0; nt < 4; nt++) {
      const int row = bm * 128 + wm * 64 + mt * 16 + gid;
      const int col = bn * 128 + wn * 32 + nt * 8 + 2 * tig;
      const float b0 = bias[col], b1 = bias[col + 1];
      float2 lo, hi;
      lo.x = acc[mt * 4 + nt][0] + b0;
      lo.y = acc[mt * 4 + nt][1] + b1;
      hi.x = acc[mt * 4 + nt][2] + b0;
      hi.y = acc[mt * 4 + nt][3] + b1;
      if (MODE == 0) {
        const int which = col / C_DIM;
        const int rem = col - which * C_DIM;
        const int h = rem >> 6, d = rem & 63;
        float* dst = (which == 0) ? g_q : (which == 1 ? g_k : g_v);
        *(float2*)&dst[((size_t)h * N_TOK + row) * D_DIM + d] = lo;
        *(float2*)&dst[((size_t)h * N_TOK + row + 8) * D_DIM + d] = hi;
      } else {
        *(float2*)&Cout[(size_t)row * C_DIM + col] = lo;
        *(float2*)&Cout[(size_t)(row + 8) * C_DIM + col] = hi;
      }
    }
  }
}

// ---------------------------------------------------------------------------
// TF32 mma flash attention (round-3 shape: 16 q-rows/warp, 128-q CTA, occ 2)
// + split K/V staging with cross-phase register prefetch:
//   V(t) LDG issues after the K barrier, lands during QK^T compute;
//   K(t+1) LDG issues after the V barrier, lands during PV compute.
// + Ks stride 72->68 (kills 2-way conflict on K b-fragment loads).
// ---------------------------------------------------------------------------
#define QST 68   // Qs/Ps stride: a-frag bank = 4*gid+tig, conflict-free
#define KST 68   // Ks stride:    k b-frag bank = 4*gid+tig, conflict-free
#define VST 72   // Vs stride:    v b-frag bank = 8*tig+gid, conflict-free
#define ATTN_SMEM ((128 * QST + 64 * KST + 64 * VST + 128 * QST) * 4)
#define NTILE ((K_COV * P_TOK) / 64)

__global__ __launch_bounds__(256, 2) void attn_kernel(
    const int* __restrict__ covis) {
  extern __shared__ unsigned sm[];
  unsigned* Qs = sm;                    // [128][QST]
  unsigned* Ks = Qs + 128 * QST;        // [64][KST]  key-major
  unsigned* Vs = Ks + 64 * KST;         // [64][VST]  key-major
  unsigned* Ps = Vs + 64 * VST;         // [128][QST]

  const int tid = threadIdx.x;
  const int warp = tid >> 5, lane = tid & 31;
  const int gid = lane >> 2, tig = lane & 3;
  const int qt = blockIdx.x, h = blockIdx.y, f = blockIdx.z;

  // staging coords: each thread covers 4 rows (one per j), 4 cols
  const int srow = tid >> 4;            // 0..15
  const int sc4 = (tid & 15) << 2;      // 0,4,...,60

  // Stage Q tile (fp32 -> tf32): 128 x 64
  const float* qptr = g_q + ((size_t)h * N_TOK + f * P_TOK + qt * 128) * D_DIM;
#pragma unroll
  for (int j = 0; j < 8; j++) {
    int i = j * 256 + tid;
    int row = i >> 4, c4 = (i & 15) << 2;
    *(uint4*)&Qs[row * QST + c4] = tf4(*(const float4*)&qptr[row * D_DIM + c4]);
  }

  float o[8][4];
#pragma unroll
  for (int nb = 0; nb < 8; nb++)
#pragma unroll
    for (int j = 0; j < 4; j++) o[nb][j] = 0.f;
  float m0 = -INFINITY, m1 = -INFINITY, l0 = 0.f, l1 = 0.f;
  const float CS = 0.18033688011f;  // 0.125 * log2(e)

  const unsigned* Qw = Qs + warp * 16 * QST;
  unsigned* Pw = Ps + warp * 16 * QST;

  const size_t hbase = (size_t)h * N_TOK;

  // Prologue: prefetch K(0)
  float4 kreg[4], vreg[4];
  {
    const int frame = covis[f * K_COV];
    const float* kp = g_k + (hbase + frame * P_TOK) * D_DIM;
#pragma unroll
    for (int j = 0; j < 4; j++)
      kreg[j] = *(const float4*)&kp[(j * 16 + srow) * D_DIM + sc4];
  }

  for (int t = 0; t < NTILE; t++) {
    const int frame = covis[f * K_COV + (t >> 3)];
    const int off = (t & 7) << 6;

    // ---- stage K(t) from prefetch regs ----
    // (safe: all warps passed last tile's second barrier after QK(t-1))
#pragma unroll
    for (int j = 0; j < 4; j++)
      *(uint4*)&Ks[(j * 16 + srow) * KST + sc4] = tf4(kreg[j]);
    __syncthreads();

    // ---- issue V(t) LDG; lands during QK compute ----
    {
      const float* vp = g_v + (hbase + frame * P_TOK + off) * D_DIM;
#pragma unroll
      for (int j = 0; j < 4; j++)
        vreg[j] = *(const float4*)&vp[(j * 16 + srow) * D_DIM + sc4];
    }

    // ---- S = Q K^T (warp computes 16x64) ----
    float s[8][4];
#pragma unroll
    for (int nb = 0; nb < 8; nb++)
#pragma unroll
      for (int j = 0; j < 4; j++) s[nb][j] = 0.f;
#pragma unroll
    for (int ks = 0; ks < 8; ks++) {
      unsigned a[4];
      a[0] = Qw[gid * QST + ks * 8 + tig];
      a[1] = Qw[(gid + 8) * QST + ks * 8 + tig];
      a[2] = Qw[gid * QST + ks * 8 + tig + 4];
      a[3] = Qw[(gid + 8) * QST + ks * 8 + tig + 4];
#pragma unroll
      for (int nb = 0; nb < 8; nb++) {
        unsigned b[2];
        b[0] = Ks[(nb * 8 + gid) * KST + ks * 8 + tig];
        b[1] = Ks[(nb * 8 + gid) * KST + ks * 8 + tig + 4];
        mma8(s[nb], a, b);
      }
    }

    // ---- online softmax ----
    float mx0 = -INFINITY, mx1 = -INFINITY;
#pragma unroll
    for (int nb = 0; nb < 8; nb++) {
      mx0 = fmaxf(mx0, fmaxf(s[nb][0], s[nb][1]));
      mx1 = fmaxf(mx1, fmaxf(s[nb][2], s[nb][3]));
    }
    mx0 = fmaxf(mx0, __shfl_xor_sync(0xffffffffu, mx0, 1));
    mx0 = fmaxf(mx0, __shfl_xor_sync(0xffffffffu, mx0, 2));
    mx1 = fmaxf(mx1, __shfl_xor_sync(0xffffffffu, mx1, 1));
    mx1 = fmaxf(mx1, __shfl_xor_sync(0xffffffffu, mx1, 2));
    const float nm0 = fmaxf(m0, mx0), nm1 = fmaxf(m1, mx1);
    const float rf0 = ex2((m0 - nm0) * CS), rf1 = ex2((m1 - nm1) * CS);
    m0 = nm0; m1 = nm1;

    float sum0 = 0.f, sum1 = 0.f;
#pragma unroll
    for (int nb = 0; nb < 8; nb++) {
      float p0 = ex2((s[nb][0] - m0) * CS);
      float p1 = ex2((s[nb][1] - m0) * CS);
      float p2 = ex2((s[nb][2] - m1) * CS);
      float p3 = ex2((s[nb][3] - m1) * CS);
      sum0 += p0 + p1;
      sum1 += p2 + p3;
      uint2 u01; u01.x = f2tf(p0); u01.y = f2tf(p1);
      uint2 u23; u23.x = f2tf(p2); u23.y = f2tf(p3);
      *(uint2*)&Pw[gid * QST + nb * 8 + 2 * tig] = u01;
      *(uint2*)&Pw[(gid + 8) * QST + nb * 8 + 2 * tig] = u23;
    }
    sum0 += __shfl_xor_sync(0xffffffffu, sum0, 1);
    sum0 += __shfl_xor_sync(0xffffffffu, sum0, 2);
    sum1 += __shfl_xor_sync(0xffffffffu, sum1, 1);
    sum1 += __shfl_xor_sync(0xffffffffu, sum1, 2);
    l0 = l0 * rf0 + sum0;
    l1 = l1 * rf1 + sum1;
#pragma unroll
    for (int nb = 0; nb < 8; nb++) {
      o[nb][0] *= rf0; o[nb][1] *= rf0;
      o[nb][2] *= rf1; o[nb][3] *= rf1;
    }

    // ---- stage V(t) (prev PV readers finished before this tile's barrier) ----
#pragma unroll
    for (int j = 0; j < 4; j++)
      *(uint4*)&Vs[(j * 16 + srow) * VST + sc4] = tf4(vreg[j]);
    __syncthreads();

    // ---- issue K(t+1) LDG; lands during PV compute ----
    if (t + 1 < NTILE) {
      const int nfr = covis[f * K_COV + ((t + 1) >> 3)];
      const int noff = ((t + 1) & 7) << 6;
      const float* kp = g_k + (hbase + nfr * P_TOK + noff) * D_DIM;
#pragma unroll
      for (int j = 0; j < 4; j++)
        kreg[j] = *(const float4*)&kp[(j * 16 + srow) * D_DIM + sc4];
    }

    // ---- O += P V ----
#pragma unroll
    for (int ks = 0; ks < 8; ks++) {
      unsigned a[4];
      a[0] = Pw[gid * QST + ks * 8 + tig];
      a[1] = Pw[(gid + 8) * QST + ks * 8 + tig];
      a[2] = Pw[gid * QST + ks * 8 + tig + 4];
      a[3] = Pw[(gid + 8) * QST + ks * 8 + tig + 4];
#pragma unroll
      for (int nb = 0; nb < 8; nb++) {
        unsigned b[2];
        b[0] = Vs[(ks * 8 + tig) * VST + nb * 8 + gid];
        b[1] = Vs[(ks * 8 + tig + 4) * VST + nb * 8 + gid];
        mma8(o[nb], a, b);
      }
    }
    __syncwarp();  // warp's P reads done before next-tile softmax overwrites
  }

  // ---- finalize: O / l, write [N, H*D] ----
  const float inv0 = 1.f / l0, inv1 = 1.f / l1;
  const int tok0 = f * P_TOK + qt * 128 + warp * 16 + gid;
  float* op0 = g_attn + (size_t)tok0 * C_DIM + h * D_DIM;
  float* op1 = op0 + 8 * C_DIM;
#pragma unroll
  for (int nb = 0; nb < 8; nb++) {
    float2 w0, w1;
    w0.x = o[nb][0] * inv0; w0.y = o[nb][1] * inv0;
    w1.x = o[nb][2] * inv1; w1.y = o[nb][3] * inv1;
    *(float2*)&op0[nb * 8 + 2 * tig] = w0;
    *(float2*)&op1[nb * 8 + 2 * tig] = w1;
  }
}

// ---------------------------------------------------------------------------
extern "C" void kernel_launch(void* const* d_in, const int* in_sizes, int n_in,
                              void* d_out, int out_size) {
  const float* x     = (const float*)d_in[0];
  const float* Wqkv  = (const float*)d_in[1];
  const float* bqkv  = (const float*)d_in[2];
  const float* Wproj = (const float*)d_in[3];
  const float* bproj = (const float*)d_in[4];
  const int*   covis = (const int*)d_in[5];
  float* out = (float*)d_out;
  (void)in_sizes; (void)n_in; (void)out_size;

  cudaFuncSetAttribute(attn_kernel, cudaFuncAttributeMaxDynamicSharedMemorySize,
                       ATTN_SMEM);

  gemm_mma<0><<<dim3(QKV_N / 128, N_TOK / 128), 256>>>(x, Wqkv, bqkv,
                                                       nullptr, QKV_N);
  attn_kernel<<<dim3(P_TOK / 128, H_HEADS, S_FR), 256, ATTN_SMEM>>>(covis);
  gemm_mma<1><<<dim3(C_DIM / 128, N_TOK / 128), 256>>>(nullptr, Wproj, bproj,
                                                       out, C_DIM);
}

// round 7
// speedup vs baseline: 1.5671x; 1.0678x over previous
#include <cuda_runtime.h>
#include <math.h>

#define S_FR   16
#define P_TOK  512
#define C_DIM  768
#define H_HEADS 12
#define K_COV  6
#define D_DIM  64
#define N_TOK  8192
#define QKV_N  2304

// Scratch (allocation-free: __device__ globals)
__device__ float g_q[H_HEADS * N_TOK * D_DIM];
__device__ float g_k[H_HEADS * N_TOK * D_DIM];
__device__ float g_v[H_HEADS * N_TOK * D_DIM];
__device__ float g_attn[N_TOK * C_DIM];

__device__ __forceinline__ unsigned f2tf(float f) {
  unsigned u;
  asm("cvt.rna.tf32.f32 %0, %1;" : "=r"(u) : "f"(f));
  return u;
}
__device__ __forceinline__ float ex2(float x) {
  float y;
  asm("ex2.approx.ftz.f32 %0, %1;" : "=f"(y) : "f"(x));
  return y;
}
__device__ __forceinline__ void mma8(float c[4], const unsigned a[4],
                                     const unsigned b[2]) {
  asm volatile(
      "mma.sync.aligned.m16n8k8.row.col.f32.tf32.tf32.f32 "
      "{%0,%1,%2,%3},{%4,%5,%6,%7},{%8,%9},{%0,%1,%2,%3};\n"
      : "+f"(c[0]), "+f"(c[1]), "+f"(c[2]), "+f"(c[3])
      : "r"(a[0]), "r"(a[1]), "r"(a[2]), "r"(a[3]), "r"(b[0]), "r"(b[1]));
}
__device__ __forceinline__ uint4 tf4(float4 v) {
  uint4 t;
  t.x = f2tf(v.x); t.y = f2tf(v.y); t.z = f2tf(v.z); t.w = f2tf(v.w);
  return t;
}
__device__ __forceinline__ uint4 tf4s(float4 v, float c) {
  uint4 t;
  t.x = f2tf(v.x * c); t.y = f2tf(v.y * c);
  t.z = f2tf(v.z * c); t.w = f2tf(v.w * c);
  return t;
}

// ---------------------------------------------------------------------------
// TF32 mma GEMM (unchanged, round-3 proven): C = A[M,768]*B[768,N] + bias
// ---------------------------------------------------------------------------
#define AST 20
#define BST 136

template <int MODE>
__global__ __launch_bounds__(256) void gemm_mma(
    const float* __restrict__ A, const float* __restrict__ B,
    const float* __restrict__ bias, float* __restrict__ Cout, int Ncols) {
  __shared__ unsigned As[128 * AST];
  __shared__ unsigned Bs[16 * BST];
  const int tid = threadIdx.x;
  const int warp = tid >> 5, lane = tid & 31;
  const int gid = lane >> 2, tig = lane & 3;
  const int wm = warp >> 2, wn = warp & 3;
  const int bn = blockIdx.x, bm = blockIdx.y;

  const float* Ap = (MODE == 1) ? (const float*)g_attn : A;
  const float* Ab = Ap + (size_t)(bm * 128) * C_DIM;
  const float* Bb = B + bn * 128;

  const int arow = tid >> 2, acol = (tid & 3) << 2;
  const int brow = tid >> 5, bcol = (tid & 31) << 2;

  float acc[16][4];
#pragma unroll
  for (int i = 0; i < 16; i++)
#pragma unroll
    for (int j = 0; j < 4; j++) acc[i][j] = 0.f;

  float4 pa0, pa1, pb0, pb1;
  pa0 = *(const float4*)&Ab[(size_t)arow * C_DIM + acol];
  pa1 = *(const float4*)&Ab[(size_t)(arow + 64) * C_DIM + acol];
  pb0 = *(const float4*)&Bb[(size_t)brow * Ncols + bcol];
  pb1 = *(const float4*)&Bb[(size_t)(brow + 8) * Ncols + bcol];

  const int NT = C_DIM / 16;
  for (int t = 0; t < NT; t++) {
    __syncthreads();
    *(uint4*)&As[arow * AST + acol] = tf4(pa0);
    *(uint4*)&As[(arow + 64) * AST + acol] = tf4(pa1);
    *(uint4*)&Bs[brow * BST + bcol] = tf4(pb0);
    *(uint4*)&Bs[(brow + 8) * BST + bcol] = tf4(pb1);
    __syncthreads();

    if (t + 1 < NT) {
      const int k0 = (t + 1) * 16;
      pa0 = *(const float4*)&Ab[(size_t)arow * C_DIM + k0 + acol];
      pa1 = *(const float4*)&Ab[(size_t)(arow + 64) * C_DIM + k0 + acol];
      pb0 = *(const float4*)&Bb[(size_t)(k0 + brow) * Ncols + bcol];
      pb1 = *(const float4*)&Bb[(size_t)(k0 + brow + 8) * Ncols + bcol];
    }

#pragma unroll
    for (int ks = 0; ks < 2; ks++) {
      const int k = ks * 8;
      unsigned af[4][4], bf[4][2];
#pragma unroll
      for (int mt = 0; mt < 4; mt++) {
        const int m = wm * 64 + mt * 16 + gid;
        af[mt][0] = As[m * AST + k + tig];
        af[mt][1] = As[(m + 8) * AST + k + tig];
        af[mt][2] = As[m * AST + k + tig + 4];
        af[mt][3] = As[(m + 8) * AST + k + tig + 4];
      }
#pragma unroll
      for (int nt = 0; nt < 4; nt++) {
        const int n = wn * 32 + nt * 8 + gid;
        bf[nt][0] = Bs[(k + tig) * BST + n];
        bf[nt][1] = Bs[(k + tig + 4) * BST + n];
      }
#pragma unroll
      for (int mt = 0; mt < 4; mt++)
#pragma unroll
        for (int nt = 0; nt < 4; nt++) mma8(acc[mt * 4 + nt], af[mt], bf[nt]);
    }
  }

#pragma unroll
  for (int mt = 0; mt < 4; mt++) {
#pragma unroll
    for (int nt = 0; nt < 4; nt++) {
      const int row = bm * 128 + wm * 64 + mt * 16 + gid;
      const int col = bn * 128 + wn * 32 + nt * 8 + 2 * tig;
      const float b0 = bias[col], b1 = bias[col + 1];
      float2 lo, hi;
      lo.x = acc[mt * 4 + nt][0] + b0;
      lo.y = acc[mt * 4 + nt][1] + b1;
      hi.x = acc[mt * 4 + nt][2] + b0;
      hi.y = acc[mt * 4 + nt][3] + b1;
      if (MODE == 0) {
        const int which = col / C_DIM;
        const int rem = col - which * C_DIM;
        const int h = rem >> 6, d = rem & 63;
        float* dst = (which == 0) ? g_q : (which == 1 ? g_k : g_v);
        *(float2*)&dst[((size_t)h * N_TOK + row) * D_DIM + d] = lo;
        *(float2*)&dst[((size_t)h * N_TOK + row + 8) * D_DIM + d] = hi;
      } else {
        *(float2*)&Cout[(size_t)row * C_DIM + col] = lo;
        *(float2*)&Cout[(size_t)(row + 8) * C_DIM + col] = hi;
      }
    }
  }
}

// ---------------------------------------------------------------------------
// TF32 mma flash attention v3:
//  - 4 warps x 32 q-rows = 128-q CTA, 128 threads, occ 2 (8 warps/SM)
//  - b-fragments (K and V) reused by 2 m-tiles  -> 0.67x smem crossbar bytes
//  - round-5 split K/V register prefetch retained
//  - Q pre-scaled by 0.125*log2(e) at staging (softmax in base-2 domain)
// ---------------------------------------------------------------------------
#define QST 68   // Qs/Ps stride: a-frag bank = 4*gid+tig, conflict-free
#define KST 68   // Ks stride:    k b-frag bank = 4*gid+tig, conflict-free
#define VST 72   // Vs stride:    v b-frag bank = 8*tig+gid, conflict-free
#define ATTN_SMEM ((128 * QST + 64 * KST + 64 * VST + 128 * QST) * 4)
#define NTILE ((K_COV * P_TOK) / 64)

__global__ __launch_bounds__(128, 2) void attn_kernel(
    const int* __restrict__ covis) {
  extern __shared__ unsigned sm[];
  unsigned* Qs = sm;                    // [128][QST]
  unsigned* Ks = Qs + 128 * QST;        // [64][KST]  key-major
  unsigned* Vs = Ks + 64 * KST;         // [64][VST]  key-major
  unsigned* Ps = Vs + 64 * VST;         // [128][QST]

  const int tid = threadIdx.x;
  const int warp = tid >> 5, lane = tid & 31;
  const int gid = lane >> 2, tig = lane & 3;
  const int qt = blockIdx.x, h = blockIdx.y, f = blockIdx.z;

  // K/V staging coords: thread covers 8 rows (krow + 8j), 4 cols
  const int krow = tid >> 4;            // 0..7
  const int kc4 = (tid & 15) << 2;      // 0,4,...,60

  const float CS = 0.18033688011f;      // 0.125 * log2(e)

  // Stage Q tile (fp32 -> tf32, pre-scaled): 128 x 64
  const float* qptr = g_q + ((size_t)h * N_TOK + f * P_TOK + qt * 128) * D_DIM;
#pragma unroll
  for (int j = 0; j < 16; j++) {
    int i = j * 128 + tid;
    int row = i >> 4, c4 = (i & 15) << 2;
    *(uint4*)&Qs[row * QST + c4] =
        tf4s(*(const float4*)&qptr[row * D_DIM + c4], CS);
  }

  float o[2][8][4];
#pragma unroll
  for (int mt = 0; mt < 2; mt++)
#pragma unroll
    for (int nb = 0; nb < 8; nb++)
#pragma unroll
      for (int j = 0; j < 4; j++) o[mt][nb][j] = 0.f;
  float mrow[2][2], lrow[2][2];
#pragma unroll
  for (int mt = 0; mt < 2; mt++) {
    mrow[mt][0] = -INFINITY; mrow[mt][1] = -INFINITY;
    lrow[mt][0] = 0.f; lrow[mt][1] = 0.f;
  }

  const unsigned* Qw = Qs + warp * 32 * QST;
  unsigned* Pw = Ps + warp * 32 * QST;

  const size_t hbase = (size_t)h * N_TOK;

  // Prologue: prefetch K(0)
  float4 kreg[8], vreg[8];
  {
    const int frame = covis[f * K_COV];
    const float* kp = g_k + (hbase + frame * P_TOK) * D_DIM;
#pragma unroll
    for (int j = 0; j < 8; j++)
      kreg[j] = *(const float4*)&kp[(j * 8 + krow) * D_DIM + kc4];
  }

  for (int t = 0; t < NTILE; t++) {
    const int frame = covis[f * K_COV + (t >> 3)];
    const int off = (t & 7) << 6;

    // ---- stage K(t) from prefetch regs ----
#pragma unroll
    for (int j = 0; j < 8; j++)
      *(uint4*)&Ks[(j * 8 + krow) * KST + kc4] = tf4(kreg[j]);
    __syncthreads();

    // ---- issue V(t) LDG; lands during QK compute ----
    {
      const float* vp = g_v + (hbase + frame * P_TOK + off) * D_DIM;
#pragma unroll
      for (int j = 0; j < 8; j++)
        vreg[j] = *(const float4*)&vp[(j * 8 + krow) * D_DIM + kc4];
    }

    // ---- S = Q K^T : warp computes 32x64 (2 m-tiles share b-frags) ----
    float s[2][8][4];
#pragma unroll
    for (int mt = 0; mt < 2; mt++)
#pragma unroll
      for (int nb = 0; nb < 8; nb++)
#pragma unroll
        for (int j = 0; j < 4; j++) s[mt][nb][j] = 0.f;
#pragma unroll
    for (int ks = 0; ks < 8; ks++) {
      unsigned a[2][4];
#pragma unroll
      for (int mt = 0; mt < 2; mt++) {
        const int r = mt * 16 + gid;
        a[mt][0] = Qw[r * QST + ks * 8 + tig];
        a[mt][1] = Qw[(r + 8) * QST + ks * 8 + tig];
        a[mt][2] = Qw[r * QST + ks * 8 + tig + 4];
        a[mt][3] = Qw[(r + 8) * QST + ks * 8 + tig + 4];
      }
#pragma unroll
      for (int nb = 0; nb < 8; nb++) {
        unsigned b[2];
        b[0] = Ks[(nb * 8 + gid) * KST + ks * 8 + tig];
        b[1] = Ks[(nb * 8 + gid) * KST + ks * 8 + tig + 4];
        mma8(s[0][nb], a[0], b);
        mma8(s[1][nb], a[1], b);
      }
    }

    // ---- online softmax (base-2 domain; Q pre-scaled) + P store ----
#pragma unroll
    for (int mt = 0; mt < 2; mt++) {
      float mx0 = -INFINITY, mx1 = -INFINITY;
#pragma unroll
      for (int nb = 0; nb < 8; nb++) {
        mx0 = fmaxf(mx0, fmaxf(s[mt][nb][0], s[mt][nb][1]));
        mx1 = fmaxf(mx1, fmaxf(s[mt][nb][2], s[mt][nb][3]));
      }
      mx0 = fmaxf(mx0, __shfl_xor_sync(0xffffffffu, mx0, 1));
      mx0 = fmaxf(mx0, __shfl_xor_sync(0xffffffffu, mx0, 2));
      mx1 = fmaxf(mx1, __shfl_xor_sync(0xffffffffu, mx1, 1));
      mx1 = fmaxf(mx1, __shfl_xor_sync(0xffffffffu, mx1, 2));
      const float nm0 = fmaxf(mrow[mt][0], mx0);
      const float nm1 = fmaxf(mrow[mt][1], mx1);
      const float rf0 = ex2(mrow[mt][0] - nm0);
      const float rf1 = ex2(mrow[mt][1] - nm1);
      mrow[mt][0] = nm0; mrow[mt][1] = nm1;

      float sum0 = 0.f, sum1 = 0.f;
      const int r = mt * 16 + gid;
#pragma unroll
      for (int nb = 0; nb < 8; nb++) {
        float p0 = ex2(s[mt][nb][0] - nm0);
        float p1 = ex2(s[mt][nb][1] - nm0);
        float p2 = ex2(s[mt][nb][2] - nm1);
        float p3 = ex2(s[mt][nb][3] - nm1);
        sum0 += p0 + p1;
        sum1 += p2 + p3;
        uint2 u01; u01.x = f2tf(p0); u01.y = f2tf(p1);
        uint2 u23; u23.x = f2tf(p2); u23.y = f2tf(p3);
        *(uint2*)&Pw[r * QST + nb * 8 + 2 * tig] = u01;
        *(uint2*)&Pw[(r + 8) * QST + nb * 8 + 2 * tig] = u23;
      }
      sum0 += __shfl_xor_sync(0xffffffffu, sum0, 1);
      sum0 += __shfl_xor_sync(0xffffffffu, sum0, 2);
      sum1 += __shfl_xor_sync(0xffffffffu, sum1, 1);
      sum1 += __shfl_xor_sync(0xffffffffu, sum1, 2);
      lrow[mt][0] = lrow[mt][0] * rf0 + sum0;
      lrow[mt][1] = lrow[mt][1] * rf1 + sum1;
#pragma unroll
      for (int nb = 0; nb < 8; nb++) {
        o[mt][nb][0] *= rf0; o[mt][nb][1] *= rf0;
        o[mt][nb][2] *= rf1; o[mt][nb][3] *= rf1;
      }
    }

    // ---- stage V(t) (all PV(t-1) reads done: they precede this tile's
    //      first barrier on every warp) ----
#pragma unroll
    for (int j = 0; j < 8; j++)
      *(uint4*)&Vs[(j * 8 + krow) * VST + kc4] = tf4(vreg[j]);
    __syncthreads();

    // ---- issue K(t+1) LDG; lands during PV compute ----
    if (t + 1 < NTILE) {
      const int nfr = covis[f * K_COV + ((t + 1) >> 3)];
      const int noff = ((t + 1) & 7) << 6;
      const float* kp = g_k + (hbase + nfr * P_TOK + noff) * D_DIM;
#pragma unroll
      for (int j = 0; j < 8; j++)
        kreg[j] = *(const float4*)&kp[(j * 8 + krow) * D_DIM + kc4];
    }

    // ---- O += P V (2 m-tiles share V b-frags) ----
#pragma unroll
    for (int ks = 0; ks < 8; ks++) {
      unsigned a[2][4];
#pragma unroll
      for (int mt = 0; mt < 2; mt++) {
        const int r = mt * 16 + gid;
        a[mt][0] = Pw[r * QST + ks * 8 + tig];
        a[mt][1] = Pw[(r + 8) * QST + ks * 8 + tig];
        a[mt][2] = Pw[r * QST + ks * 8 + tig + 4];
        a[mt][3] = Pw[(r + 8) * QST + ks * 8 + tig + 4];
      }
#pragma unroll
      for (int nb = 0; nb < 8; nb++) {
        unsigned b[2];
        b[0] = Vs[(ks * 8 + tig) * VST + nb * 8 + gid];
        b[1] = Vs[(ks * 8 + tig + 4) * VST + nb * 8 + gid];
        mma8(o[0][nb], a[0], b);
        mma8(o[1][nb], a[1], b);
      }
    }
    __syncwarp();  // warp's P reads done before next-tile softmax overwrites
  }

  // ---- finalize: O / l, write [N, H*D] ----
#pragma unroll
  for (int mt = 0; mt < 2; mt++) {
    const float inv0 = 1.f / lrow[mt][0], inv1 = 1.f / lrow[mt][1];
    const int tok0 = f * P_TOK + qt * 128 + warp * 32 + mt * 16 + gid;
    float* op0 = g_attn + (size_t)tok0 * C_DIM + h * D_DIM;
    float* op1 = op0 + 8 * C_DIM;
#pragma unroll
    for (int nb = 0; nb < 8; nb++) {
      float2 w0, w1;
      w0.x = o[mt][nb][0] * inv0; w0.y = o[mt][nb][1] * inv0;
      w1.x = o[mt][nb][2] * inv1; w1.y = o[mt][nb][3] * inv1;
      *(float2*)&op0[nb * 8 + 2 * tig] = w0;
      *(float2*)&op1[nb * 8 + 2 * tig] = w1;
    }
  }
}

// ---------------------------------------------------------------------------
extern "C" void kernel_launch(void* const* d_in, const int* in_sizes, int n_in,
                              void* d_out, int out_size) {
  const float* x     = (const float*)d_in[0];
  const float* Wqkv  = (const float*)d_in[1];
  const float* bqkv  = (const float*)d_in[2];
  const float* Wproj = (const float*)d_in[3];
  const float* bproj = (const float*)d_in[4];
  const int*   covis = (const int*)d_in[5];
  float* out = (float*)d_out;
  (void)in_sizes; (void)n_in; (void)out_size;

  cudaFuncSetAttribute(attn_kernel, cudaFuncAttributeMaxDynamicSharedMemorySize,
                       ATTN_SMEM);

  gemm_mma<0><<<dim3(QKV_N / 128, N_TOK / 128), 256>>>(x, Wqkv, bqkv,
                                                       nullptr, QKV_N);
  attn_kernel<<<dim3(P_TOK / 128, H_HEADS, S_FR), 128, ATTN_SMEM>>>(covis);
  gemm_mma<1><<<dim3(C_DIM / 128, N_TOK / 128), 256>>>(nullptr, Wproj, bproj,
                                                       out, C_DIM);
}